// round 2
// baseline (speedup 1.0000x reference)
#include <cuda_runtime.h>

#define FULLMASK 0xFFFFFFFFu

// ---- problem constants (B=8, grids 13/26/52, 3 anchors, 80 classes) ----
#define CPI0 507          // 13*13*3 cells per image
#define CPI1 2028         // 26*26*3
#define CPI2 8112         // 52*52*3
#define CELLS0 4056       // * 8 images
#define CELLS1 16224
#define CELLS2 64896
#define TOTCELLS 85176

#define NB0 64
#define NB1 160
#define NB2 640
#define NBTOT 864

static __constant__ int   c_gh[3] = {13, 26, 52};
static __constant__ float c_anch[3][3][2] = {
    {{116.f, 90.f}, {156.f, 198.f}, {373.f, 326.f}},   // mask [6,7,8]
    {{ 30.f, 61.f}, { 62.f,  45.f}, { 59.f, 119.f}},   // mask [3,4,5]
    {{ 10.f, 13.f}, { 16.f,  30.f}, { 33.f,  23.f}}};  // mask [0,1,2]

// ---- static device scratch (no allocations allowed) ----
__device__ double       g_part[NBTOT][6];   // per-block partials: sxy, swh, sconf, scls, sobjscale, cobj
__device__ unsigned int g_nvalid[24];       // [layer*8 + image]
__device__ unsigned int g_cign[3];          // per-layer Σ (1-obj)*ignore (exact integer)
__device__ float4       g_boxes[TOTCELLS * 2]; // compacted true boxes: {xmin,ymin,xmax,ymax},{area,_,_,_}

__device__ __forceinline__ float bcef(float z, float x) {
    // max(x,0) - x*z + log1p(exp(-|x|))
    return fmaxf(x, 0.f) - x * z + log1pf(expf(-fabsf(x)));
}

__global__ void k_zero() {
    int t = threadIdx.x;
    if (t < 24) g_nvalid[t] = 0u;
    if (t < 3)  g_cign[t]   = 0u;
}

// One warp per cell. Lanes cover the 85 channels (lane, lane+32, lane+64).
__global__ void __launch_bounds__(256) k_main(
    const float* __restrict__ o0, const float* __restrict__ l0,
    const float* __restrict__ o1, const float* __restrict__ l1,
    const float* __restrict__ o2, const float* __restrict__ l2)
{
    int bId = blockIdx.x;
    int layer, lb, nblk, cells, cpi, cellbase;
    const float* op; const float* lp;
    if (bId < NB0)            { layer = 0; lb = bId;            nblk = NB0; cells = CELLS0; cpi = CPI0; op = o0; lp = l0; cellbase = 0; }
    else if (bId < NB0 + NB1) { layer = 1; lb = bId - NB0;      nblk = NB1; cells = CELLS1; cpi = CPI1; op = o1; lp = l1; cellbase = CELLS0; }
    else                      { layer = 2; lb = bId - NB0 - NB1; nblk = NB2; cells = CELLS2; cpi = CPI2; op = o2; lp = l2; cellbase = CELLS0 + CELLS1; }

    const int gh = c_gh[layer];
    const int gw = gh;
    const float gwf = (float)gw, ghf = (float)gh;
    const float iw = gwf * 32.f, ih = ghf * 32.f;

    const int lane  = threadIdx.x & 31;
    const int warp  = threadIdx.x >> 5;
    const int gwarp = lb * 8 + warp;
    const int nwarps = nblk * 8;

    double sxy = 0, swh = 0, sconf = 0, scls = 0, sos = 0, cobj = 0;

    for (int cell = gwarp; cell < cells; cell += nwarps) {
        int b  = cell / cpi;
        int r  = cell - b * cpi;
        int y  = r / (gw * 3);
        int r2 = r - y * (gw * 3);
        int x  = r2 / 3;
        int a  = r2 - x * 3;
        int base = (((b * gh) + y) * gw + x) * 255 + a * 85;
        const float* fz = lp + base;
        const float* ff = op + base;

        float z0 = fz[lane],      f0 = ff[lane];
        float z1 = fz[lane + 32], f1 = ff[lane + 32];
        float z2 = 0.f, f2 = 0.f;
        if (lane < 21) { z2 = fz[lane + 64]; f2 = ff[lane + 64]; }

        float obj = __shfl_sync(FULLMASK, z0, 4);
        float lxv = __shfl_sync(FULLMASK, z0, 0);
        float lyv = __shfl_sync(FULLMASK, z0, 1);
        float lwv = __shfl_sync(FULLMASK, z0, 2);
        float lhv = __shfl_sync(FULLMASK, z0, 3);
        float scale = 2.f - lwv * lhv;
        float aw = c_anch[layer][a][0], ah = c_anch[layer][a][1];

        if (lane == 0) {
            sxy  += (double)bcef(z0 * gwf - (float)x, f0);
            sos  += (double)(obj * scale);
            cobj += (double)obj;
            if (obj != 0.f) {   // compact valid true box (precompute min/max/area)
                unsigned slot = atomicAdd(&g_nvalid[layer * 8 + b], 1u);
                int e = cellbase + b * cpi + (int)slot;
                float hw = lwv * 0.5f, hh = lhv * 0.5f;
                g_boxes[2 * e]     = make_float4(lxv - hw, lyv - hh, lxv + hw, lyv + hh);
                g_boxes[2 * e + 1] = make_float4(lwv * lhv, 0.f, 0.f, 0.f);
            }
        } else if (lane == 1) {
            sxy += (double)bcef(z0 * ghf - (float)y, f0);
        } else if (lane == 2) {
            float tz = logf(z0 * iw / aw);
            float d  = tz - f0;
            swh += (double)(obj * scale * 0.5f * d * d);
        } else if (lane == 3) {
            float tz = logf(z0 * ih / ah);
            float d  = tz - f0;
            swh += (double)(obj * scale * 0.5f * d * d);
        } else if (lane == 4) {
            sconf += (double)bcef(z0, f0);
        } else {
            scls += (double)bcef(z0, f0);
        }
        scls += (double)bcef(z1, f1);
        if (lane < 21) scls += (double)bcef(z2, f2);
    }

    // deterministic block reduce -> per-block partial slot
    double vals[6] = {sxy, swh, sconf, scls, sos, cobj};
    __shared__ double sh[8][6];
#pragma unroll
    for (int i = 0; i < 6; i++) {
        double v = vals[i];
        for (int off = 16; off; off >>= 1) v += __shfl_down_sync(FULLMASK, v, off);
        if (lane == 0) sh[warp][i] = v;
    }
    __syncthreads();
    if (threadIdx.x < 6) {
        double s = 0;
        for (int w = 0; w < 8; w++) s += sh[w][threadIdx.x];
        g_part[bId][threadIdx.x] = s;
    }
}

// One thread per cell: best (buggy) IoU vs this image's valid boxes; exact int count.
__global__ void __launch_bounds__(256) k_ignore(
    const float* __restrict__ o0, const float* __restrict__ l0,
    const float* __restrict__ o1, const float* __restrict__ l1,
    const float* __restrict__ o2, const float* __restrict__ l2)
{
    __shared__ unsigned int shc[3];
    if (threadIdx.x < 3) shc[threadIdx.x] = 0u;
    __syncthreads();

    int idx = blockIdx.x * blockDim.x + threadIdx.x;
    if (idx < TOTCELLS) {
        int layer, cell, cpi, cellbase;
        const float* op; const float* lp;
        if (idx < CELLS0)              { layer = 0; cell = idx;                   cpi = CPI0; op = o0; lp = l0; cellbase = 0; }
        else if (idx < CELLS0 + CELLS1){ layer = 1; cell = idx - CELLS0;          cpi = CPI1; op = o1; lp = l1; cellbase = CELLS0; }
        else                           { layer = 2; cell = idx - CELLS0 - CELLS1; cpi = CPI2; op = o2; lp = l2; cellbase = CELLS0 + CELLS1; }

        const int gh = c_gh[layer];
        const int gw = gh;
        int b  = cell / cpi;
        int r  = cell - b * cpi;
        int y  = r / (gw * 3);
        int r2 = r - y * (gw * 3);
        int x  = r2 / 3;
        int a  = r2 - x * 3;
        int base = (((b * gh) + y) * gw + x) * 255 + a * 85;

        float f0  = op[base],     f1 = op[base + 1];
        float f2v = op[base + 2], f3 = op[base + 3];
        float obj = lp[base + 4];
        float aw = c_anch[layer][a][0], ah = c_anch[layer][a][1];
        float gwf = (float)gw, ghf = (float)gh;

        float px = (1.f / (1.f + expf(-f0)) + (float)x) / gwf;
        float py = (1.f / (1.f + expf(-f1)) + (float)y) / ghf;
        float pw = expf(f2v) * aw / (gwf * 32.f);
        float ph = expf(f3)  * ah / (ghf * 32.f);

        float b1x0 = px - pw * 0.5f, b1y0 = py - ph * 0.5f;
        float b1x1 = px + pw * 0.5f, b1y1 = py + ph * 0.5f;
        float a1 = pw * ph;

        int n  = (int)g_nvalid[layer * 8 + b];
        int e0 = cellbase + b * cpi;
        float best = -1.f;   // reference masks invalid with -1; empty list -> -1
        for (int j = 0; j < n; j++) {
            float4 mm = g_boxes[2 * (e0 + j)];
            float  a2 = g_boxes[2 * (e0 + j) + 1].x;
            float ix0 = fmaxf(b1x0, mm.x);
            float iy0 = fmaxf(b1y0, mm.y);
            float ix1 = fmaxf(b1x1, mm.z);   // NOTE: reference uses maximum here (its bug) — replicate
            float iy1 = fmaxf(b1y1, mm.w);
            float iww = fmaxf(ix1 - ix0, 0.f);
            float ihh = fmaxf(iy1 - iy0, 0.f);
            float inter = iww * ihh;
            float iou = inter / (a1 + a2 - inter);
            best = fmaxf(best, iou);
        }
        if (obj == 0.f && best < 0.5f)
            atomicAdd(&shc[layer], 1u);
    }
    __syncthreads();
    if (threadIdx.x < 3 && shc[threadIdx.x])
        atomicAdd(&g_cign[threadIdx.x], shc[threadIdx.x]);
}

// Deterministic reduce of per-block partials + final scalar combine.
__global__ void __launch_bounds__(576) k_final(float* __restrict__ out) {
    __shared__ double res[3][6];
    int w = threadIdx.x >> 5, lane = threadIdx.x & 31;
    if (w < 18) {
        int layer = w / 6, val = w - layer * 6;
        int start = (layer == 0) ? 0 : (layer == 1) ? NB0 : (NB0 + NB1);
        int cnt   = (layer == 0) ? NB0 : (layer == 1) ? NB1 : NB2;
        double s = 0;
        for (int i = lane; i < cnt; i += 32) s += g_part[start + i][val];
        for (int off = 16; off; off >>= 1) s += __shfl_down_sync(FULLMASK, s, off);
        if (lane == 0) res[layer][val] = s;
    }
    __syncthreads();
    if (threadIdx.x == 0) {
        const int cpis[3] = {CPI0, CPI1, CPI2};
        double loss = 0;
        for (int l = 0; l < 3; l++) {
            double N     = 8.0 * (double)cpis[l];     // B*gh*gw*3 elements
            double mxy   = res[l][0] / (N * 2.0);
            double mconf = res[l][2] / N;
            double mcls  = res[l][3] / (N * 80.0);
            double sos   = res[l][4];
            double cobj  = res[l][5];
            loss += mxy * sos                       // xy_loss * B
                  + res[l][1]                        // wh_loss * B
                  + mconf * (cobj + (double)g_cign[l])  // conf_loss * B
                  + mcls * cobj;                     // class_loss * B
        }
        *out = (float)(loss / 8.0);
    }
}

extern "C" void kernel_launch(void* const* d_in, const int* in_sizes, int n_in,
                              void* d_out, int out_size) {
    const float *O[3], *L[3];
    // o_i and l_i have equal element counts per layer; layers differ.
    // interleaved order (o0,l0,o1,l1,o2,l2) <=> sizes[0]==sizes[1].
    if (in_sizes[0] == in_sizes[1]) {
        O[0] = (const float*)d_in[0]; L[0] = (const float*)d_in[1];
        O[1] = (const float*)d_in[2]; L[1] = (const float*)d_in[3];
        O[2] = (const float*)d_in[4]; L[2] = (const float*)d_in[5];
    } else {
        O[0] = (const float*)d_in[0]; O[1] = (const float*)d_in[1]; O[2] = (const float*)d_in[2];
        L[0] = (const float*)d_in[3]; L[1] = (const float*)d_in[4]; L[2] = (const float*)d_in[5];
    }
    k_zero<<<1, 32>>>();
    k_main<<<NBTOT, 256>>>(O[0], L[0], O[1], L[1], O[2], L[2]);
    k_ignore<<<(TOTCELLS + 255) / 256, 256>>>(O[0], L[0], O[1], L[1], O[2], L[2]);
    k_final<<<1, 576>>>((float*)d_out);
}

// round 3
// speedup vs baseline: 2.7722x; 2.7722x over previous
#include <cuda_runtime.h>

#define FULLMASK 0xFFFFFFFFu

// ---- problem constants (B=8, grids 13/26/52, 3 anchors, 80 classes) ----
#define CPI0 507          // 13*13*3 cells per image
#define CPI1 2028         // 26*26*3
#define CPI2 8112         // 52*52*3
#define CELLS0 4056       // * 8 images
#define CELLS1 16224
#define CELLS2 64896
#define TOTCELLS 85176

#define NB0 64
#define NB1 160
#define NB2 640
#define NBTOT 864
#define IGN_BLOCKS ((TOTCELLS + 255) / 256)   // 333

static __constant__ int   c_gh[3] = {13, 26, 52};
static __constant__ float c_anch[3][3][2] = {
    {{116.f, 90.f}, {156.f, 198.f}, {373.f, 326.f}},   // mask [6,7,8]
    {{ 30.f, 61.f}, { 62.f,  45.f}, { 59.f, 119.f}},   // mask [3,4,5]
    {{ 10.f, 13.f}, { 16.f,  30.f}, { 33.f,  23.f}}};  // mask [0,1,2]

// ---- static device scratch (no allocations allowed) ----
__device__ double       g_part[6][NBTOT];   // SoA per-block partials: sxy,swh,sconf,scls,sos,cobj
__device__ unsigned int g_nvalid[24];       // [layer*8 + image]
__device__ unsigned int g_cign[3];          // per-layer exact ignore counts (obj==0 cells)
__device__ unsigned int g_done;             // completion counter for fused final reduce
__device__ float4       g_boxes[TOTCELLS];  // compacted valid true boxes: {xmin,ymin,xmax,ymax}

__device__ __forceinline__ float bcef(float z, float x) {
    // max(x,0) - x*z + log1p(exp(-|x|))
    return fmaxf(x, 0.f) - x * z + log1pf(expf(-fabsf(x)));
}

__global__ void k_zero() {
    int t = threadIdx.x;
    if (t < 24) g_nvalid[t] = 0u;
    if (t < 3)  g_cign[t]   = 0u;
    if (t == 31) g_done     = 0u;
}

// One warp per cell. Lanes cover the 85 channels (lane, lane+32, lane+64).
// All-float hot loop (FP64 only at per-block partial write), branch-free accumulation.
__global__ void __launch_bounds__(256) k_main(
    const float* __restrict__ o0, const float* __restrict__ l0,
    const float* __restrict__ o1, const float* __restrict__ l1,
    const float* __restrict__ o2, const float* __restrict__ l2)
{
    int bId = blockIdx.x;
    int layer, lb, nblk, cells, cpi, cellbase;
    const float* op; const float* lp;
    if (bId < NB0)             { layer = 0; lb = bId;             nblk = NB0; cells = CELLS0; cpi = CPI0; op = o0; lp = l0; cellbase = 0; }
    else if (bId < NB0 + NB1)  { layer = 1; lb = bId - NB0;       nblk = NB1; cells = CELLS1; cpi = CPI1; op = o1; lp = l1; cellbase = CELLS0; }
    else                       { layer = 2; lb = bId - NB0 - NB1; nblk = NB2; cells = CELLS2; cpi = CPI2; op = o2; lp = l2; cellbase = CELLS0 + CELLS1; }

    const int   gw  = c_gh[layer];             // grid is square: gh==gw
    const float gwf = (float)gw;
    const float iw  = gwf * 32.f;              // input size (square)

    const int lane   = threadIdx.x & 31;
    const int warp   = threadIdx.x >> 5;
    const int gwarp  = lb * 8 + warp;
    const int nwarps = nblk * 8;

    // loop-invariant lane masks
    const float m_xy   = (lane < 2)  ? 1.f : 0.f;
    const float m_conf = (lane == 4) ? 1.f : 0.f;
    const float m_cls0 = (lane > 4)  ? 1.f : 0.f;
    const float m_l0   = (lane == 0) ? 1.f : 0.f;
    const bool  has2   = (lane < 21);
    const float m_cls2 = has2 ? 1.f : 0.f;
    const bool  is_wh  = (lane == 2) || (lane == 3);

    float sxy = 0.f, swh = 0.f, sconf = 0.f, scls = 0.f, sos = 0.f, cobj = 0.f;

    for (int cell = gwarp; cell < cells; cell += nwarps) {
        int a  = cell % 3;
        int c3 = cell / 3;
        int x  = c3 % gw;
        int y  = (c3 / gw) % gw;               // gh==gw
        const float* fz = lp + (size_t)cell * 85;   // base = cell*85 (contiguous layout)
        const float* ff = op + (size_t)cell * 85;

        float z0 = fz[lane],      f0 = ff[lane];
        float z1 = fz[lane + 32], f1 = ff[lane + 32];
        float z2 = has2 ? fz[lane + 64] : 0.f;
        float f2 = has2 ? ff[lane + 64] : 0.f;

        float obj = __shfl_sync(FULLMASK, z0, 4);
        float lwv = __shfl_sync(FULLMASK, z0, 2);
        float lhv = __shfl_sync(FULLMASK, z0, 3);
        float scale = 2.f - lwv * lhv;
        float aw = c_anch[layer][a][0], ah = c_anch[layer][a][1];

        // lane 0: z*gw - x ; lane 1: z*gh - y ; others: raw
        float zm = z0;
        if (lane == 0) zm = z0 * gwf - (float)x;
        else if (lane == 1) zm = z0 * gwf - (float)y;

        float v0 = bcef(zm, f0);
        float v1 = bcef(z1, f1);
        float v2 = bcef(z2, f2);

        // wh term (valid for lanes 2,3; clamp keeps it finite on other lanes so the
        // select can't see NaN/inf)
        float anchor = (lane == 3) ? ah : aw;
        float t   = logf(fmaxf(z0, 1e-12f) * iw / anchor) - f0;
        float whv = (obj * scale * 0.5f) * t * t;

        sxy   += m_xy   * v0;
        sconf += m_conf * v0;
        scls  += m_cls0 * v0 + v1 + m_cls2 * v2;
        swh   += is_wh ? whv : 0.f;
        sos   += m_l0 * (obj * scale);
        cobj  += m_l0 * obj;

        if (lane == 0 && obj != 0.f) {   // rare (~2%): compact valid true box
            int b = cell / cpi;
            unsigned slot = atomicAdd(&g_nvalid[layer * 8 + b], 1u);
            int e = cellbase + b * cpi + (int)slot;
            float lxv = __shfl_sync(0x1u, z0, 0); // lane 0 only path; z0 already local
            lxv = z0;                              // lane 0's z0 is label x
            float lyv = 0.f;                       // fetch y directly (cheap, rare)
            lyv = fz[1];
            float hw = lwv * 0.5f, hh = lhv * 0.5f;
            g_boxes[e] = make_float4(lxv - hw, lyv - hh, lxv + hw, lyv + hh);
        }
    }

    // float warp reduce -> shared -> double per-block partial (FP64 only here)
    float vals[6] = {sxy, swh, sconf, scls, sos, cobj};
    __shared__ float sh[6][8];
#pragma unroll
    for (int i = 0; i < 6; i++) {
        float v = vals[i];
        for (int off = 16; off; off >>= 1) v += __shfl_down_sync(FULLMASK, v, off);
        if (lane == 0) sh[i][warp] = v;
    }
    __syncthreads();
    if (threadIdx.x < 6) {
        double s = 0.0;
        for (int w = 0; w < 8; w++) s += (double)sh[threadIdx.x][w];
        g_part[threadIdx.x][bId] = s;
    }
}

// One thread per cell: division-free best-IoU-threshold test against this image's
// valid boxes (replicating the reference's inter_maxes = maximum(b1max,b2max) bug).
// Last block performs the final reduction and writes the loss.
__global__ void __launch_bounds__(256) k_ignore(
    const float* __restrict__ o0, const float* __restrict__ l0,
    const float* __restrict__ o1, const float* __restrict__ l1,
    const float* __restrict__ o2, const float* __restrict__ l2,
    float* __restrict__ out)
{
    __shared__ unsigned int shc[3];
    __shared__ bool s_last;
    if (threadIdx.x < 3) shc[threadIdx.x] = 0u;
    __syncthreads();

    int idx = blockIdx.x * blockDim.x + threadIdx.x;
    if (idx < TOTCELLS) {
        int layer, cell, cpi, cellbase;
        const float* op; const float* lp;
        if (idx < CELLS0)               { layer = 0; cell = idx;                   cpi = CPI0; op = o0; lp = l0; cellbase = 0; }
        else if (idx < CELLS0 + CELLS1) { layer = 1; cell = idx - CELLS0;          cpi = CPI1; op = o1; lp = l1; cellbase = CELLS0; }
        else                            { layer = 2; cell = idx - CELLS0 - CELLS1; cpi = CPI2; op = o2; lp = l2; cellbase = CELLS0 + CELLS1; }

        const int gw = c_gh[layer];
        int a  = cell % 3;
        int c3 = cell / 3;
        int x  = c3 % gw;
        int y  = (c3 / gw) % gw;
        int b  = cell / cpi;
        const float* ff = op + (size_t)cell * 85;

        float f0  = ff[0], f1 = ff[1], f2v = ff[2], f3 = ff[3];
        float obj = lp[(size_t)cell * 85 + 4];
        float aw = c_anch[layer][a][0], ah = c_anch[layer][a][1];
        float gwf = (float)gw;

        float px = (1.f / (1.f + expf(-f0)) + (float)x) / gwf;
        float py = (1.f / (1.f + expf(-f1)) + (float)y) / gwf;
        float pw = expf(f2v) * aw / (gwf * 32.f);
        float ph = expf(f3)  * ah / (gwf * 32.f);

        float b1x0 = px - pw * 0.5f, b1y0 = py - ph * 0.5f;
        float b1x1 = px + pw * 0.5f, b1y1 = py + ph * 0.5f;
        float a1 = pw * ph;

        int n  = (int)g_nvalid[layer * 8 + b];
        int e0 = cellbase + b * cpi;
        bool hit = false;   // any box with iou >= 0.5
        for (int j = 0; j < n; j++) {
            float4 mm = g_boxes[e0 + j];
            float a2  = (mm.z - mm.x) * (mm.w - mm.y);
            float ix0 = fmaxf(b1x0, mm.x);
            float iy0 = fmaxf(b1y0, mm.y);
            float ix1 = fmaxf(b1x1, mm.z);   // reference bug: max of maxes — replicate
            float iy1 = fmaxf(b1y1, mm.w);
            float iww = fmaxf(ix1 - ix0, 0.f);
            float ihh = fmaxf(iy1 - iy0, 0.f);
            float inter = iww * ihh;
            float D = a1 + a2 - inter;
            // iou >= 0.5  <=>  D > 0 && 2*inter >= D   (D<=0 => iou<=0 < 0.5)
            hit = hit || ((D > 0.f) && (2.f * inter >= D));
        }
        if (obj == 0.f && !hit)
            atomicAdd(&shc[layer], 1u);
    }
    __syncthreads();
    if (threadIdx.x < 3 && shc[threadIdx.x])
        atomicAdd(&g_cign[threadIdx.x], shc[threadIdx.x]);
    __syncthreads();
    if (threadIdx.x == 0) {
        __threadfence();
        unsigned t = atomicAdd(&g_done, 1u);
        s_last = (t == (unsigned)(IGN_BLOCKS - 1));
    }
    __syncthreads();
    if (!s_last) return;

    // ---- fused final reduce (runs in exactly one block, after all others) ----
    __threadfence();
    __shared__ double res[3][6];
    int w = threadIdx.x >> 5, lane = threadIdx.x & 31;
    for (int task = w; task < 18; task += 8) {
        int layer = task / 6, val = task - layer * 6;
        int start = (layer == 0) ? 0 : (layer == 1) ? NB0 : (NB0 + NB1);
        int cnt   = (layer == 0) ? NB0 : (layer == 1) ? NB1 : NB2;
        double s = 0.0;
        for (int i = lane; i < cnt; i += 32) s += g_part[val][start + i];
        for (int off = 16; off; off >>= 1) s += __shfl_down_sync(FULLMASK, s, off);
        if (lane == 0) res[layer][val] = s;
    }
    __syncthreads();
    if (threadIdx.x == 0) {
        const int cpis[3] = {CPI0, CPI1, CPI2};
        double loss = 0.0;
        for (int l = 0; l < 3; l++) {
            double N     = 8.0 * (double)cpis[l];     // B*gh*gw*3 elements
            double mxy   = res[l][0] / (N * 2.0);
            double mconf = res[l][2] / N;
            double mcls  = res[l][3] / (N * 80.0);
            loss += mxy * res[l][4]                              // xy_loss * B
                  + res[l][1]                                    // wh_loss * B
                  + mconf * (res[l][5] + (double)g_cign[l])      // conf_loss * B
                  + mcls * res[l][5];                            // class_loss * B
        }
        *out = (float)(loss / 8.0);
    }
}

extern "C" void kernel_launch(void* const* d_in, const int* in_sizes, int n_in,
                              void* d_out, int out_size) {
    const float *O[3], *L[3];
    // o_i and l_i have equal element counts per layer; layers differ.
    // interleaved order (o0,l0,o1,l1,o2,l2) <=> sizes[0]==sizes[1].
    if (in_sizes[0] == in_sizes[1]) {
        O[0] = (const float*)d_in[0]; L[0] = (const float*)d_in[1];
        O[1] = (const float*)d_in[2]; L[1] = (const float*)d_in[3];
        O[2] = (const float*)d_in[4]; L[2] = (const float*)d_in[5];
    } else {
        O[0] = (const float*)d_in[0]; O[1] = (const float*)d_in[1]; O[2] = (const float*)d_in[2];
        L[0] = (const float*)d_in[3]; L[1] = (const float*)d_in[4]; L[2] = (const float*)d_in[5];
    }
    k_zero<<<1, 32>>>();
    k_main<<<NBTOT, 256>>>(O[0], L[0], O[1], L[1], O[2], L[2]);
    k_ignore<<<IGN_BLOCKS, 256>>>(O[0], L[0], O[1], L[1], O[2], L[2], (float*)d_out);
}

// round 4
// speedup vs baseline: 3.9077x; 1.4096x over previous
#include <cuda_runtime.h>

#define FULLMASK 0xFFFFFFFFu

// ---- problem constants (B=8, grids 13/26/52, 3 anchors, 80 classes) ----
#define CPI0 507          // 13*13*3 cells per image
#define CPI1 2028
#define CPI2 8112
#define CELLS0 4056       // * 8 images
#define CELLS1 16224
#define CELLS2 64896
#define TOTCELLS 85176

// persistent grid: 4 blocks/SM * 148 SMs = 592, guaranteed co-resident
#define GRID 592
#define B0S 0
#define B0N 28
#define B1S 28
#define B1N 112
#define B2S 140
#define B2N 452           // 28+112+452 = 592, ~18 cells/warp everywhere

static __constant__ float c_anch[3][3][2] = {
    {{116.f, 90.f}, {156.f, 198.f}, {373.f, 326.f}},   // mask [6,7,8]
    {{ 30.f, 61.f}, { 62.f,  45.f}, { 59.f, 119.f}},   // mask [3,4,5]
    {{ 10.f, 13.f}, { 16.f,  30.f}, { 33.f,  23.f}}};  // mask [0,1,2]

// ---- static device scratch (zero-initialized at module load; self-reset each run) ----
__device__ double       g_part[6][GRID];    // per-block partials: sxy,swh,sconf,scls,sos,cobj
__device__ unsigned int g_nvalid[24];       // [layer*8 + image]
__device__ unsigned int g_cign[3];          // per-layer exact ignore counts
__device__ unsigned int g_bar1, g_bar2;     // grid barrier / completion counters
__device__ float4       g_boxes[TOTCELLS];  // compacted valid true boxes {xmin,ymin,xmax,ymax}

__device__ __forceinline__ float bcef_fast(float z, float x) {
    // max(x,0) - x*z + log1p(exp(-|x|)), MUFU-direct (err ~2^-21, sums tolerate it)
    return fmaxf(x, 0.f) - x * z + __logf(1.f + __expf(-fabsf(x)));
}

// ---------------- phase 1: per-layer main sums + valid-box compaction ----------------
template<int LAYER, int GW, int CPI, int CELLS, int CELLBASE, int BSTART, int NBLK>
__device__ __forceinline__ void phase1(const float* __restrict__ op,
                                       const float* __restrict__ lp,
                                       float* s, int bId, int lane, int warp)
{
    const float gwf = (float)GW;
    const float iw  = gwf * 32.f;
    const int gwarp  = (bId - BSTART) * 8 + warp;
    const int nwarps = NBLK * 8;

    const float m_xy   = (lane < 2)  ? 1.f : 0.f;
    const float m_conf = (lane == 4) ? 1.f : 0.f;
    const float m_cls0 = (lane > 4)  ? 1.f : 0.f;
    const float m_l0   = (lane == 0) ? 1.f : 0.f;
    const bool  has2   = (lane < 21);
    const bool  is_wh  = (lane == 2) || (lane == 3);

    for (int cell = gwarp; cell < CELLS; cell += nwarps) {
        int a  = cell % 3;                 // compile-time divisors -> magic mul
        int c3 = cell / 3;
        int x  = c3 % GW;
        int y  = (c3 / GW) % GW;
        const float* fz = lp + (size_t)cell * 85;
        const float* ff = op + (size_t)cell * 85;

        float z0 = fz[lane],      f0 = ff[lane];
        float z1 = fz[lane + 32], f1 = ff[lane + 32];
        float z2 = has2 ? fz[lane + 64] : 0.f;
        float f2 = has2 ? ff[lane + 64] : 0.f;

        float obj = __shfl_sync(FULLMASK, z0, 4);
        float lwv = __shfl_sync(FULLMASK, z0, 2);
        float lhv = __shfl_sync(FULLMASK, z0, 3);
        float scale = 2.f - lwv * lhv;

        float zm = z0;
        if (lane == 0)      zm = z0 * gwf - (float)x;
        else if (lane == 1) zm = z0 * gwf - (float)y;

        float v0 = bcef_fast(zm, f0);
        float v1 = bcef_fast(z1, f1);
        float v2 = has2 ? bcef_fast(z2, f2) : 0.f;

        float anchor = (lane == 3) ? c_anch[LAYER][a][1] : c_anch[LAYER][a][0];
        float t   = __logf(fmaxf(z0, 1e-12f) * iw / anchor) - f0;
        float whv = (obj * scale * 0.5f) * t * t;

        s[0] += m_xy   * v0;
        s[2] += m_conf * v0;
        s[3] += m_cls0 * v0 + v1 + v2;
        s[1] += is_wh ? whv : 0.f;
        s[4] += m_l0 * (obj * scale);
        s[5] += m_l0 * obj;

        if (lane == 0 && obj != 0.f) {     // rare (~2%)
            int b = cell / CPI;
            unsigned slot = atomicAdd(&g_nvalid[LAYER * 8 + b], 1u);
            int e = CELLBASE + b * CPI + (int)slot;
            float lyv = fz[1];
            float hw = lwv * 0.5f, hh = lhv * 0.5f;
            g_boxes[e] = make_float4(z0 - hw, lyv - hh, z0 + hw, lyv + hh);
        }
    }
}

// ---------------- phase 2: per-cell ignore test (division-free, replicates ref's
// inter_maxes = maximum(b1max,b2max) bug) ----------------
template<int LAYER, int GW, int CPI, int CELLBASE>
__device__ __forceinline__ bool cell_hit(const float* __restrict__ op,
                                         const float* __restrict__ lp,
                                         int cell, float* obj_out)
{
    int a  = cell % 3;
    int c3 = cell / 3;
    int x  = c3 % GW;
    int y  = (c3 / GW) % GW;
    int b  = cell / CPI;
    const float* ff = op + (size_t)cell * 85;
    float f0 = ff[0], f1 = ff[1], f2v = ff[2], f3 = ff[3];
    *obj_out = lp[(size_t)cell * 85 + 4];

    const float gwf = (float)GW;
    float aw = c_anch[LAYER][a][0], ah = c_anch[LAYER][a][1];
    // precise expf here: keeps the integer ignore count bit-stable vs reference
    float px = (1.f / (1.f + expf(-f0)) + (float)x) / gwf;
    float py = (1.f / (1.f + expf(-f1)) + (float)y) / gwf;
    float pw = expf(f2v) * aw / (gwf * 32.f);
    float ph = expf(f3)  * ah / (gwf * 32.f);

    float b1x0 = px - pw * 0.5f, b1y0 = py - ph * 0.5f;
    float b1x1 = px + pw * 0.5f, b1y1 = py + ph * 0.5f;
    float a1 = pw * ph;

    int n  = (int)__ldcg(&g_nvalid[LAYER * 8 + b]);
    int e0 = CELLBASE + b * CPI;
    bool hit = false;
    for (int j = 0; j < n; j++) {
        float4 mm = __ldcg(&g_boxes[e0 + j]);
        float a2  = (mm.z - mm.x) * (mm.w - mm.y);
        float ix0 = fmaxf(b1x0, mm.x);
        float iy0 = fmaxf(b1y0, mm.y);
        float ix1 = fmaxf(b1x1, mm.z);   // reference bug: max of maxes — replicate
        float iy1 = fmaxf(b1y1, mm.w);
        float iww = fmaxf(ix1 - ix0, 0.f);
        float ihh = fmaxf(iy1 - iy0, 0.f);
        float inter = iww * ihh;
        float D = a1 + a2 - inter;
        // iou >= 0.5  <=>  D > 0 && 2*inter >= D
        hit = hit || ((D > 0.f) && (2.f * inter >= D));
    }
    return hit;
}

// ---------------- fused persistent kernel ----------------
__global__ void __launch_bounds__(256, 4) k_fused(
    const float* __restrict__ o0, const float* __restrict__ l0,
    const float* __restrict__ o1, const float* __restrict__ l1,
    const float* __restrict__ o2, const float* __restrict__ l2,
    float* __restrict__ out)
{
    const int bId  = blockIdx.x;
    const int lane = threadIdx.x & 31;
    const int warp = threadIdx.x >> 5;

    // ---- phase 1 ----
    float s[6] = {0.f, 0.f, 0.f, 0.f, 0.f, 0.f};
    if (bId < B1S)      phase1<0, 13, CPI0, CELLS0, 0,             B0S, B0N>(o0, l0, s, bId, lane, warp);
    else if (bId < B2S) phase1<1, 26, CPI1, CELLS1, CELLS0,        B1S, B1N>(o1, l1, s, bId, lane, warp);
    else                phase1<2, 52, CPI2, CELLS2, CELLS0+CELLS1, B2S, B2N>(o2, l2, s, bId, lane, warp);

    __shared__ float sh[6][8];
#pragma unroll
    for (int i = 0; i < 6; i++) {
        float v = s[i];
        for (int off = 16; off; off >>= 1) v += __shfl_down_sync(FULLMASK, v, off);
        if (lane == 0) sh[i][warp] = v;
    }
    __syncthreads();
    if (threadIdx.x < 6) {
        double d = 0.0;
        for (int w = 0; w < 8; w++) d += (double)sh[threadIdx.x][w];
        g_part[threadIdx.x][bId] = d;
    }

    // ---- grid barrier (all 592 blocks co-resident by launch_bounds) ----
    __syncthreads();
    if (threadIdx.x == 0) {
        __threadfence();
        atomicAdd(&g_bar1, 1u);
        while (*(volatile unsigned int*)&g_bar1 < GRID) { }
    }
    __syncthreads();

    // ---- phase 2 ----
    __shared__ unsigned int shc[3];
    __shared__ bool s_last;
    if (threadIdx.x < 3) shc[threadIdx.x] = 0u;
    __syncthreads();

    int idx = bId * 256 + threadIdx.x;
    if (idx < TOTCELLS) {
        float obj; bool hit; int layer;
        if (idx < CELLS0)               { layer = 0; hit = cell_hit<0, 13, CPI0, 0>            (o0, l0, idx, &obj); }
        else if (idx < CELLS0 + CELLS1) { layer = 1; hit = cell_hit<1, 26, CPI1, CELLS0>       (o1, l1, idx - CELLS0, &obj); }
        else                            { layer = 2; hit = cell_hit<2, 52, CPI2, CELLS0+CELLS1>(o2, l2, idx - CELLS0 - CELLS1, &obj); }
        if (obj == 0.f && !hit) atomicAdd(&shc[layer], 1u);
    }
    __syncthreads();
    if (threadIdx.x < 3 && shc[threadIdx.x]) atomicAdd(&g_cign[threadIdx.x], shc[threadIdx.x]);
    __syncthreads();
    if (threadIdx.x == 0) {
        __threadfence();
        unsigned t = atomicAdd(&g_bar2, 1u);
        s_last = (t == (unsigned)(GRID - 1));
    }
    __syncthreads();
    if (!s_last) return;

    // ---- final reduce + combine (exactly one block, after all others finished) ----
    __shared__ double res[3][6];
    for (int task = warp; task < 18; task += 8) {
        int layer = task / 6, val = task - layer * 6;
        int start = (layer == 0) ? B0S : (layer == 1) ? B1S : B2S;
        int cnt   = (layer == 0) ? B0N : (layer == 1) ? B1N : B2N;
        double d = 0.0;
        for (int i = lane; i < cnt; i += 32) d += __ldcg(&g_part[val][start + i]);
        for (int off = 16; off; off >>= 1) d += __shfl_down_sync(FULLMASK, d, off);
        if (lane == 0) res[layer][val] = d;
    }
    __syncthreads();
    if (threadIdx.x == 0) {
        const int cpis[3] = {CPI0, CPI1, CPI2};
        double loss = 0.0;
        for (int l = 0; l < 3; l++) {
            double N     = 8.0 * (double)cpis[l];
            double mxy   = res[l][0] / (N * 2.0);
            double mconf = res[l][2] / N;
            double mcls  = res[l][3] / (N * 80.0);
            unsigned ci  = *(volatile unsigned int*)&g_cign[l];
            loss += mxy * res[l][4]                          // xy_loss * B
                  + res[l][1]                                // wh_loss * B
                  + mconf * (res[l][5] + (double)ci)         // conf_loss * B
                  + mcls * res[l][5];                        // class_loss * B
        }
        *out = (float)(loss / 8.0);
    }
    __syncthreads();
    // self-reset for the next graph replay (initial state is zero-init at load)
    if (threadIdx.x < 24)                       g_nvalid[threadIdx.x] = 0u;
    if (threadIdx.x >= 24 && threadIdx.x < 27)  g_cign[threadIdx.x - 24] = 0u;
    if (threadIdx.x == 30)                      g_bar1 = 0u;
    if (threadIdx.x == 31)                      g_bar2 = 0u;
}

extern "C" void kernel_launch(void* const* d_in, const int* in_sizes, int n_in,
                              void* d_out, int out_size) {
    const float *O[3], *L[3];
    // o_i and l_i have equal element counts per layer; layers differ.
    // interleaved order (o0,l0,o1,l1,o2,l2) <=> sizes[0]==sizes[1].
    if (in_sizes[0] == in_sizes[1]) {
        O[0] = (const float*)d_in[0]; L[0] = (const float*)d_in[1];
        O[1] = (const float*)d_in[2]; L[1] = (const float*)d_in[3];
        O[2] = (const float*)d_in[4]; L[2] = (const float*)d_in[5];
    } else {
        O[0] = (const float*)d_in[0]; O[1] = (const float*)d_in[1]; O[2] = (const float*)d_in[2];
        L[0] = (const float*)d_in[3]; L[1] = (const float*)d_in[4]; L[2] = (const float*)d_in[5];
    }
    k_fused<<<GRID, 256>>>(O[0], L[0], O[1], L[1], O[2], L[2], (float*)d_out);
}